// round 16
// baseline (speedup 1.0000x reference)
#include <cuda_runtime.h>
#include <cuda_bf16.h>
#include <cstdint>

#define Bb 16
#define Qq 64
#define KK 512
#define Dd 512
#define Hh 256
#define KS 32

// Scratch (device globals; no allocations allowed)
__device__ float g_qh[Bb * Qq * Hh];            // 1 MB
__device__ float g_kh[Bb * KK * Hh];            // 8 MB
__device__ float g_attn[Bb * Qq * KK];          // 2 MB (raw scores)
__device__ uint16_t g_wbf[2 * 2 * 256 * 512];   // [mat][plane][n][k] bf16, 1 MB

__device__ __forceinline__ float tanhx(float x) {
    float y;
    asm("tanh.approx.f32 %0, %1;" : "=f"(y) : "f"(x));
    return y;
}

// fp32 pair -> packed bf16x2 (hi parts) + packed bf16x2 (lo residuals)
__device__ __forceinline__ void cvt_split2(float a, float b, uint32_t& hi, uint32_t& lo) {
    uint32_t h;
    asm("cvt.rn.bf16x2.f32 %0, %1, %2;" : "=r"(h) : "f"(b), "f"(a));
    float ah = __uint_as_float(h << 16);
    float bh = __uint_as_float(h & 0xffff0000u);
    float al = a - ah, bl = b - bh;
    asm("cvt.rn.bf16x2.f32 %0, %1, %2;" : "=r"(lo) : "f"(bl), "f"(al));
    hi = h;
}
__device__ __forceinline__ void split1(float a, uint16_t& h, uint16_t& l) {
    uint32_t hw, lw;
    cvt_split2(a, 0.f, hw, lw);
    h = (uint16_t)(hw & 0xffff);
    l = (uint16_t)(lw & 0xffff);
}

#define MMA_BF16(d, a, b0v, b1v) \
    asm volatile("mma.sync.aligned.m16n8k16.row.col.f32.bf16.bf16.f32 " \
        "{%0,%1,%2,%3}, {%4,%5,%6,%7}, {%8,%9}, {%0,%1,%2,%3};" \
        : "+f"((d)[0]), "+f"((d)[1]), "+f"((d)[2]), "+f"((d)[3]) \
        : "r"((a)[0]), "r"((a)[1]), "r"((a)[2]), "r"((a)[3]), \
          "r"(b0v), "r"(b1v))

#define CP_ASYNC16(dst_u32, src_ptr) \
    asm volatile("cp.async.cg.shared.global [%0], [%1], 16;" \
        :: "r"(dst_u32), "l"(src_ptr))
#define CP_COMMIT() asm volatile("cp.async.commit_group;")
#define CP_WAIT(n)  asm volatile("cp.async.wait_group %0;" :: "n"(n))

// ===================== proj: cp.async 3-stage pipeline ======================
#define PJ_AROW 160
#define PJ_ASZ  (128 * PJ_AROW)             // 20480
#define PJ_WROW 80
#define PJ_WSZ  (64 * PJ_WROW)              // 5120
#define PJ_STG  (PJ_ASZ + 2 * PJ_WSZ)       // 30720
#define PJ_NSTG 3
#define PROJ_SMEM (PJ_NSTG * PJ_STG)        // 92160 -> 2 CTAs/SM

// prep_w: Wq/Wk fp32 [k][n] -> g_wbf bf16 hi/lo planes [mat][p][n][k].
__global__ __launch_bounds__(256) void prep_w(
        const float* __restrict__ Wq, const float* __restrict__ Wk) {
    int i = blockIdx.x * 256 + threadIdx.x;   // 0 .. 65535
    int mat = i >> 15;
    int rem = i & 32767;
    int k   = rem >> 6;
    int n4  = (rem & 63) << 2;
    const float* W = mat ? Wk : Wq;
    float4 v = *(const float4*)(W + (long)k * Hh + n4);
    float vv[4] = {v.x, v.y, v.z, v.w};
    uint16_t* hp = g_wbf + ((long)(mat * 2 + 0) * 256) * 512;
    uint16_t* lp = g_wbf + ((long)(mat * 2 + 1) * 256) * 512;
    #pragma unroll
    for (int j = 0; j < 4; j++) {
        uint16_t h, l;
        split1(vv[j], h, l);
        hp[(long)(n4 + j) * 512 + k] = h;
        lp[(long)(n4 + j) * 512 + k] = l;
    }
}

// ---------------------------------------------------------------------------
// Tensor-core proj GEMM, bf16x3 split, cp.async 3-stage / depth-2 prefetch.
// (round-14 version, masked key tiles.)
// 256 threads / 8 warps; warp = 16(M) x 64(N). grid = (4, 72), block = 256.
// ---------------------------------------------------------------------------
__global__ __launch_bounds__(256) void proj_mma(
        const float* __restrict__ queries, const float* __restrict__ keys,
        const int* __restrict__ vlens) {
    extern __shared__ __align__(16) char sm[];
    const int tid = threadIdx.x, lane = tid & 31, w = tid >> 5;
    const int row0 = blockIdx.y * 128, bn = blockIdx.x * 64;

    const float* Ap;
    float* Cp;
    int mat;
    if (row0 < Bb * Qq) {
        Ap = queries + (long)row0 * Dd; Cp = g_qh + (long)row0 * Hh; mat = 0;
    } else {
        const int krow = row0 - Bb * Qq;
        const int b    = krow >> 9;
        if ((krow & (KK - 1)) >= vlens[b]) return;   // fully-masked key tile
        Ap = keys + (long)krow * Dd; Cp = g_kh + (long)krow * Hh; mat = 1;
    }
    const uint16_t* wh = g_wbf + ((long)(mat * 2 + 0) * 256 + bn) * 512;
    const uint16_t* wl = g_wbf + ((long)(mat * 2 + 1) * 256 + bn) * 512;

    const uint32_t sbase = (uint32_t)__cvta_generic_to_shared(sm);
    const int gr = lane >> 2;
    const int c2 = (lane & 3) << 1;

    float acc[8][4] = {};

    auto issue_slice = [&](int s) {
        const uint32_t st = sbase + (s % PJ_NSTG) * PJ_STG;
        #pragma unroll
        for (int r = 0; r < 4; r++) {
            int id = tid + 256 * r;
            int row = id >> 3, c = id & 7;
            CP_ASYNC16(st + row * PJ_AROW + c * 16,
                       Ap + (long)row * Dd + s * KS + c * 4);
        }
        #pragma unroll
        for (int r = 0; r < 2; r++) {
            int id = tid + 256 * r;
            int p = id >> 8, n = (id >> 2) & 63, c = id & 3;
            const uint16_t* src = (p ? wl : wh) + (long)n * 512 + s * KS + c * 8;
            CP_ASYNC16(st + PJ_ASZ + p * PJ_WSZ + n * PJ_WROW + c * 16, src);
        }
        CP_COMMIT();
    };

    issue_slice(0);
    issue_slice(1);

    const int NS = Dd / KS;    // 16 slices
    for (int s = 0; s < NS; s++) {
        if (s + 1 < NS) { CP_WAIT(1); } else { CP_WAIT(0); }
        __syncthreads();
        if (s + 2 < NS) issue_slice(s + 2);   // writes stage (s-1)%3: consumed

        const char* sb = sm + (s % PJ_NSTG) * PJ_STG;
        const float* sA = (const float*)sb;
        const char*  sW = sb + PJ_ASZ;

        #pragma unroll
        for (int kh = 0; kh < 2; kh++) {
            const int kb = kh * 16;
            uint32_t ah[4], al[4];
            const int mr = w * 16 + gr;
            const float* pA = sA + (long)mr * 40 + kb + c2;   // 40 floats/row
            float2 f0 = *(const float2*)(pA);
            float2 f1 = *(const float2*)(pA + 8 * 40);
            float2 f2 = *(const float2*)(pA + 8);
            float2 f3 = *(const float2*)(pA + 8 * 40 + 8);
            cvt_split2(f0.x, f0.y, ah[0], al[0]);
            cvt_split2(f1.x, f1.y, ah[1], al[1]);
            cvt_split2(f2.x, f2.y, ah[2], al[2]);
            cvt_split2(f3.x, f3.y, ah[3], al[3]);
            #pragma unroll
            for (int j = 0; j < 8; j++) {
                const int nr = 8 * j + gr;
                const char* pB = sW + (long)nr * PJ_WROW + (kb + c2) * 2;
                uint32_t bh0 = *(const uint32_t*)(pB);
                uint32_t bh1 = *(const uint32_t*)(pB + 16);
                uint32_t bl0 = *(const uint32_t*)(pB + PJ_WSZ);
                uint32_t bl1 = *(const uint32_t*)(pB + PJ_WSZ + 16);
                MMA_BF16(acc[j], ah, bh0, bh1);
                MMA_BF16(acc[j], ah, bl0, bl1);
                MMA_BF16(acc[j], al, bh0, bh1);
            }
        }
        __syncthreads();   // all warps done with stage s before it is re-filled
    }

    {
        const int mr = w * 16 + gr;
        #pragma unroll
        for (int j = 0; j < 8; j++) {
            float* cp = Cp + (long)mr * Hh + bn + 8 * j + c2;
            *(float2*)cp            = make_float2(acc[j][0], acc[j][1]);
            *(float2*)(cp + 8 * Hh) = make_float2(acc[j][2], acc[j][3]);
        }
    }
}

// ---------------------------------------------------------------------------
// S1: balanced scoring pass (unchanged). Raw scores -> g_attn.
// ---------------------------------------------------------------------------
#define S1_QT 65
#define S1_KT 18
#define S1_SMEM (Hh * S1_QT * 4 + Hh * S1_KT * 4)

__global__ __launch_bounds__(256) void score_pass(
        const float* __restrict__ Wv, const int* __restrict__ vlens) {
    const int kt = blockIdx.x;
    const int b  = blockIdx.y;
    const int vl = vlens[b];
    if (kt * 16 >= vl) return;

    extern __shared__ float s1[];
    float* qt = s1;                        // [256][65]
    float* ktl = s1 + Hh * S1_QT;          // [256][18], [h][16] = Wv[h]

    const int tid  = threadIdx.x;
    const int lane = tid & 31;
    const int w    = tid >> 5;

    {
        const float4* src = (const float4*)(g_qh + (long)b * Qq * Hh);
        #pragma unroll
        for (int r = 0; r < 16; r++) {
            int i = tid + 256 * r;
            int q = i >> 6, h0 = (i & 63) << 2;
            float4 v = src[i];
            qt[(h0 + 0) * S1_QT + q] = v.x;
            qt[(h0 + 1) * S1_QT + q] = v.y;
            qt[(h0 + 2) * S1_QT + q] = v.z;
            qt[(h0 + 3) * S1_QT + q] = v.w;
        }
    }
    {
        const float4* src = (const float4*)(g_kh + ((long)b * KK + kt * 16) * Hh);
        #pragma unroll
        for (int r = 0; r < 4; r++) {
            int i = tid + 256 * r;
            int k = i >> 6, h0 = (i & 63) << 2;
            float4 v = src[i];
            ktl[(h0 + 0) * S1_KT + k] = v.x;
            ktl[(h0 + 1) * S1_KT + k] = v.y;
            ktl[(h0 + 2) * S1_KT + k] = v.z;
            ktl[(h0 + 3) * S1_KT + k] = v.w;
        }
    }
    ktl[tid * S1_KT + 16] = Wv[tid];
    __syncthreads();

    float a00 = 0.f, a01 = 0.f, a10 = 0.f, a11 = 0.f;
    #pragma unroll 4
    for (int h = 0; h < Hh; h++) {
        const float* kr = ktl + h * S1_KT;
        float2 kv = *(const float2*)(kr + 2 * w);
        float  wv = kr[16];
        float  qa = qt[h * S1_QT + lane];
        float  qb = qt[h * S1_QT + lane + 32];
        a00 = fmaf(wv, tanhx(qa + kv.x), a00);
        a01 = fmaf(wv, tanhx(qa + kv.y), a01);
        a10 = fmaf(wv, tanhx(qb + kv.x), a10);
        a11 = fmaf(wv, tanhx(qb + kv.y), a11);
    }

    float* d0 = g_attn + ((long)b * Qq + lane) * KK + kt * 16 + 2 * w;
    *(float2*)d0              = make_float2(a00, a01);
    *(float2*)(d0 + 32 * KK)  = make_float2(a10, a11);
}

// ---------------------------------------------------------------------------
// Fused softmax + AV GEMM. CTA (b, n-tile of 32): prologue computes per-row
// softmax stats (max, 1/sumexp) from raw scores; A-staging applies
// exp(x - mx) * inv (masked -> exact 0) before the bf16 hi/lo split.
// Double-buffered smem, warp = 16(M) x 32(N), K bounded at align32(vl).
// grid = (Bb, Dd/32), block = 128.
// ---------------------------------------------------------------------------
#define RS 72
#define AV_AH 0
#define AV_AL (64 * RS)
#define AV_BH (2 * 64 * RS)
#define AV_BL (AV_BH + 32 * RS)
#define AV_STG (AV_BL + 32 * RS)            // 13824 bytes
#define AV_SMEM (2 * AV_STG + 2 * 64 * 4)   // + mx[64], inv[64]

__global__ __launch_bounds__(128) void av_mma(
        const float* __restrict__ values, float* __restrict__ out,
        const int* __restrict__ vlens) {
    extern __shared__ __align__(16) char sma[];
    float* mx_s  = (float*)(sma + 2 * AV_STG);
    float* inv_s = mx_s + 64;
    const int tid = threadIdx.x, lane = tid & 31, w = tid >> 5;
    const int b = blockIdx.x, bn = blockIdx.y * 32;

    const float* Ap = g_attn + (long)b * Qq * KK;
    const float* Bp = values + (long)b * KK * Dd;
    float* Cp       = out + (long)b * Qq * Dd;
    const int vl    = vlens[b];
    const int nsl   = (((vl + 31) & ~31) >> 5);

    // ---- softmax prologue: warp w owns rows w*16 .. w*16+15 ----
    for (int rr = 0; rr < 16; rr++) {
        const int row = w * 16 + rr;
        const float4* r4 = (const float4*)(Ap + (long)row * KK);
        float vals[16];
        float mx = -3.0e38f;
        #pragma unroll
        for (int i = 0; i < 4; i++) {
            float4 t = r4[lane + 32 * i];
            int k0 = 4 * (lane + 32 * i);
            float tt[4] = {t.x, t.y, t.z, t.w};
            #pragma unroll
            for (int j = 0; j < 4; j++) {
                float x = (k0 + j < vl) ? tt[j] : -1e6f;
                vals[i * 4 + j] = x;
                mx = fmaxf(mx, x);
            }
        }
        #pragma unroll
        for (int off = 16; off; off >>= 1)
            mx = fmaxf(mx, __shfl_xor_sync(0xffffffffu, mx, off));
        float sum = 0.f;
        #pragma unroll
        for (int i = 0; i < 16; i++) sum += __expf(vals[i] - mx);
        #pragma unroll
        for (int off = 16; off; off >>= 1)
            sum += __shfl_xor_sync(0xffffffffu, sum, off);
        if (lane == 0) {
            mx_s[row]  = mx;
            inv_s[row] = __fdividef(1.f, sum);
        }
    }
    __syncthreads();

    const int gr = lane >> 2;
    const int c2 = (lane & 3) << 1;

    float acc[4][4] = {};
    float4 ra[4], rw[2];

    auto ldg_slice = [&](int s) {
        const float* Ab = Ap + s * 32;
        const float* Bb2 = Bp + (long)s * 32 * Dd;
        #pragma unroll
        for (int r = 0; r < 4; r++) {
            int i = tid + 128 * r;
            ra[r] = *(const float4*)(Ab + (long)(i >> 3) * KK + ((i & 7) << 2));
        }
        #pragma unroll
        for (int r = 0; r < 2; r++) {
            int i = tid + 128 * r;
            rw[r] = *(const float4*)(Bb2 + (long)(i >> 3) * Dd + bn + ((i & 7) << 2));
        }
    };
    auto sts_slice = [&](char* sb, int s) {
        #pragma unroll
        for (int r = 0; r < 4; r++) {
            int i = tid + 128 * r;
            int row = i >> 3, kc = (i & 7) << 2;
            const float m  = mx_s[row];
            const float iv = inv_s[row];
            const int k0 = s * 32 + kc;
            float x[4] = {ra[r].x, ra[r].y, ra[r].z, ra[r].w};
            #pragma unroll
            for (int j = 0; j < 4; j++)
                x[j] = (k0 + j < vl) ? __expf(x[j] - m) * iv : 0.f;
            uint32_t h0, l0, h1, l1;
            cvt_split2(x[0], x[1], h0, l0);
            cvt_split2(x[2], x[3], h1, l1);
            *(uint2*)(sb + AV_AH + row * RS + kc * 2) = make_uint2(h0, h1);
            *(uint2*)(sb + AV_AL + row * RS + kc * 2) = make_uint2(l0, l1);
        }
        #pragma unroll
        for (int r = 0; r < 2; r++) {
            int i = tid + 128 * r;
            int k = i >> 3, nc = (i & 7) << 2;
            float v[4] = {rw[r].x, rw[r].y, rw[r].z, rw[r].w};
            #pragma unroll
            for (int j = 0; j < 4; j++) {
                uint16_t hh, ll;
                split1(v[j], hh, ll);
                *(uint16_t*)(sb + AV_BH + (nc + j) * RS + k * 2) = hh;
                *(uint16_t*)(sb + AV_BL + (nc + j) * RS + k * 2) = ll;
            }
        }
    };

    ldg_slice(0);
    sts_slice(sma, 0);
    __syncthreads();

    for (int s = 0; s < nsl; s++) {
        const char* sb = sma + (s & 1) * AV_STG;
        if (s + 1 < nsl) ldg_slice(s + 1);

        #pragma unroll
        for (int kh = 0; kh < 2; kh++) {
            const int kb = kh * 16;
            uint32_t ah[4], al[4];
            const int mr = w * 16 + gr;
            const char* pA = sb + (long)mr * RS + (kb + c2) * 2;
            ah[0] = *(const uint32_t*)(pA + AV_AH);
            ah[1] = *(const uint32_t*)(pA + AV_AH + 8 * RS);
            ah[2] = *(const uint32_t*)(pA + AV_AH + 16);
            ah[3] = *(const uint32_t*)(pA + AV_AH + 8 * RS + 16);
            al[0] = *(const uint32_t*)(pA + AV_AL);
            al[1] = *(const uint32_t*)(pA + AV_AL + 8 * RS);
            al[2] = *(const uint32_t*)(pA + AV_AL + 16);
            al[3] = *(const uint32_t*)(pA + AV_AL + 8 * RS + 16);
            #pragma unroll
            for (int j = 0; j < 4; j++) {
                const int nr = 8 * j + gr;
                const char* pB = sb + (long)nr * RS + (kb + c2) * 2;
                uint32_t bh0 = *(const uint32_t*)(pB + AV_BH);
                uint32_t bh1 = *(const uint32_t*)(pB + AV_BH + 16);
                uint32_t bl0 = *(const uint32_t*)(pB + AV_BL);
                uint32_t bl1 = *(const uint32_t*)(pB + AV_BL + 16);
                MMA_BF16(acc[j], ah, bh0, bh1);
                MMA_BF16(acc[j], ah, bl0, bl1);
                MMA_BF16(acc[j], al, bh0, bh1);
            }
        }

        if (s + 1 < nsl) sts_slice(sma + ((s + 1) & 1) * AV_STG, s + 1);
        __syncthreads();
    }

    {
        const int mr = w * 16 + gr;
        #pragma unroll
        for (int j = 0; j < 4; j++) {
            float* cp = Cp + (long)mr * Dd + bn + 8 * j + c2;
            *(float2*)cp            = make_float2(acc[j][0], acc[j][1]);
            *(float2*)(cp + 8 * Dd) = make_float2(acc[j][2], acc[j][3]);
        }
    }
}

extern "C" void kernel_launch(void* const* d_in, const int* in_sizes, int n_in,
                              void* d_out, int out_size) {
    const float* queries = (const float*)d_in[0];  // [16,64,512]
    const float* keys    = (const float*)d_in[1];  // [16,512,512]
    const float* values  = (const float*)d_in[2];  // [16,512,512]
    const int*   vlens   = (const int*)d_in[3];    // [16]
    const float* Wq      = (const float*)d_in[4];  // [512,256]
    const float* Wk      = (const float*)d_in[5];  // [512,256]
    const float* Wv      = (const float*)d_in[6];  // [256]
    float* out = (float*)d_out;                    // [16,64,512]

    cudaFuncSetAttribute(proj_mma,
                         cudaFuncAttributeMaxDynamicSharedMemorySize, PROJ_SMEM);
    cudaFuncSetAttribute(score_pass,
                         cudaFuncAttributeMaxDynamicSharedMemorySize, S1_SMEM);
    cudaFuncSetAttribute(av_mma,
                         cudaFuncAttributeMaxDynamicSharedMemorySize, AV_SMEM);

    prep_w<<<256, 256>>>(Wq, Wk);
    proj_mma<<<dim3(Hh / 64, (Bb * Qq + Bb * KK) / 128), 256, PROJ_SMEM>>>(
        queries, keys, vlens);
    score_pass<<<dim3(KK / 16, Bb), 256, S1_SMEM>>>(Wv, vlens);
    av_mma<<<dim3(Bb, Dd / 32), 128, AV_SMEM>>>(values, out, vlens);
}

// round 17
// speedup vs baseline: 1.3306x; 1.3306x over previous
#include <cuda_runtime.h>
#include <cuda_fp16.h>
#include <cstdint>

#define Bb 16
#define Qq 64
#define KK 512
#define Dd 512
#define Hh 256
#define KS 32

// Scratch (device globals; no allocations allowed)
__device__ float g_qh[Bb * Qq * Hh];            // 1 MB
__device__ float g_kh[Bb * KK * Hh];            // 8 MB
__device__ float g_attn[Bb * Qq * KK];          // 2 MB (scores -> attn in place)
__device__ uint16_t g_whf[2 * 256 * 512];       // [mat][n][k] fp16 W, 0.5 MB

__device__ __forceinline__ float tanhx(float x) {
    float y;
    asm("tanh.approx.f32 %0, %1;" : "=f"(y) : "f"(x));
    return y;
}

// fp32 pair -> packed fp16x2 hi + packed fp16x2 lo residuals (a in low half)
__device__ __forceinline__ void cvt_split2_h(float a, float b, uint32_t& hi, uint32_t& lo) {
    uint32_t h;
    asm("cvt.rn.f16x2.f32 %0, %1, %2;" : "=r"(h) : "f"(b), "f"(a));
    float fa, fb;
    asm("{\n\t.reg .f16 x, y;\n\tmov.b32 {x, y}, %2;\n\t"
        "cvt.f32.f16 %0, x;\n\tcvt.f32.f16 %1, y;\n\t}"
        : "=f"(fa), "=f"(fb) : "r"(h));
    float ra = a - fa, rb = b - fb;
    asm("cvt.rn.f16x2.f32 %0, %1, %2;" : "=r"(lo) : "f"(rb), "f"(ra));
    hi = h;
}
__device__ __forceinline__ uint16_t f2h(float a) {
    uint16_t r;
    asm("cvt.rn.f16.f32 %0, %1;" : "=h"(r) : "f"(a));
    return r;
}

#define MMA_F16(d, a, b0v, b1v) \
    asm volatile("mma.sync.aligned.m16n8k16.row.col.f32.f16.f16.f32 " \
        "{%0,%1,%2,%3}, {%4,%5,%6,%7}, {%8,%9}, {%0,%1,%2,%3};" \
        : "+f"((d)[0]), "+f"((d)[1]), "+f"((d)[2]), "+f"((d)[3]) \
        : "r"((a)[0]), "r"((a)[1]), "r"((a)[2]), "r"((a)[3]), \
          "r"(b0v), "r"(b1v))

#define CP_ASYNC16(dst_u32, src_ptr) \
    asm volatile("cp.async.cg.shared.global [%0], [%1], 16;" \
        :: "r"(dst_u32), "l"(src_ptr))
#define CP_COMMIT() asm volatile("cp.async.commit_group;")
#define CP_WAIT(n)  asm volatile("cp.async.wait_group %0;" :: "n"(n))

// ===================== proj: cp.async 3-stage pipeline ======================
#define PJ_AROW 160
#define PJ_ASZ  (128 * PJ_AROW)             // 20480 (A raw fp32)
#define PJ_WROW 80
#define PJ_WSZ  (64 * PJ_WROW)              // 5120 (W fp16, 1 plane)
#define PJ_STG  (PJ_ASZ + PJ_WSZ)           // 25600
#define PJ_NSTG 3
#define PROJ_SMEM (PJ_NSTG * PJ_STG)        // 76800 -> 2 CTAs/SM

// prep_w: Wq/Wk fp32 [k][n] -> g_whf fp16 [mat][n][k].
__global__ __launch_bounds__(256) void prep_w(
        const float* __restrict__ Wq, const float* __restrict__ Wk) {
    int i = blockIdx.x * 256 + threadIdx.x;   // 0 .. 65535
    int mat = i >> 15;
    int rem = i & 32767;
    int k   = rem >> 6;
    int n4  = (rem & 63) << 2;
    const float* W = mat ? Wk : Wq;
    float4 v = *(const float4*)(W + (long)k * Hh + n4);
    float vv[4] = {v.x, v.y, v.z, v.w};
    uint16_t* hp = g_whf + ((long)mat * 256) * 512;
    #pragma unroll
    for (int j = 0; j < 4; j++)
        hp[(long)(n4 + j) * 512 + k] = f2h(vv[j]);
}

// ---------------------------------------------------------------------------
// Tensor-core proj GEMM, fp16x2 split (A = hi+lo, W = hi only), cp.async
// 3-stage / depth-2 prefetch. Masked key tiles skipped.
// 256 threads / 8 warps; warp = 16(M) x 64(N). grid = (4, 72), block = 256.
// ---------------------------------------------------------------------------
__global__ __launch_bounds__(256) void proj_mma(
        const float* __restrict__ queries, const float* __restrict__ keys,
        const int* __restrict__ vlens) {
    extern __shared__ __align__(16) char sm[];
    const int tid = threadIdx.x, lane = tid & 31, w = tid >> 5;
    const int row0 = blockIdx.y * 128, bn = blockIdx.x * 64;

    const float* Ap;
    float* Cp;
    int mat;
    if (row0 < Bb * Qq) {
        Ap = queries + (long)row0 * Dd; Cp = g_qh + (long)row0 * Hh; mat = 0;
    } else {
        const int krow = row0 - Bb * Qq;
        const int b    = krow >> 9;
        if ((krow & (KK - 1)) >= vlens[b]) return;   // fully-masked key tile
        Ap = keys + (long)krow * Dd; Cp = g_kh + (long)krow * Hh; mat = 1;
    }
    const uint16_t* wh = g_whf + ((long)mat * 256 + bn) * 512;

    const uint32_t sbase = (uint32_t)__cvta_generic_to_shared(sm);
    const int gr = lane >> 2;
    const int c2 = (lane & 3) << 1;

    float acc[8][4] = {};

    auto issue_slice = [&](int s) {
        const uint32_t st = sbase + (s % PJ_NSTG) * PJ_STG;
        // A: 128 rows x 128 B = 1024 chunks, 4/thread
        #pragma unroll
        for (int r = 0; r < 4; r++) {
            int id = tid + 256 * r;
            int row = id >> 3, c = id & 7;
            CP_ASYNC16(st + row * PJ_AROW + c * 16,
                       Ap + (long)row * Dd + s * KS + c * 4);
        }
        // W: 64 rows x 64 B = 256 chunks, 1/thread
        {
            int n = tid >> 2, c = tid & 3;
            CP_ASYNC16(st + PJ_ASZ + n * PJ_WROW + c * 16,
                       wh + (long)n * 512 + s * KS + c * 8);
        }
        CP_COMMIT();
    };

    issue_slice(0);
    issue_slice(1);

    const int NS = Dd / KS;    // 16 slices
    for (int s = 0; s < NS; s++) {
        if (s + 1 < NS) { CP_WAIT(1); } else { CP_WAIT(0); }
        __syncthreads();
        if (s + 2 < NS) issue_slice(s + 2);   // writes stage (s-1)%3: consumed

        const char* sb = sm + (s % PJ_NSTG) * PJ_STG;
        const float* sA = (const float*)sb;
        const char*  sW = sb + PJ_ASZ;

        #pragma unroll
        for (int kh = 0; kh < 2; kh++) {
            const int kb = kh * 16;
            uint32_t ah[4], al[4];
            const int mr = w * 16 + gr;
            const float* pA = sA + (long)mr * 40 + kb + c2;   // 40 floats/row
            float2 f0 = *(const float2*)(pA);
            float2 f1 = *(const float2*)(pA + 8 * 40);
            float2 f2 = *(const float2*)(pA + 8);
            float2 f3 = *(const float2*)(pA + 8 * 40 + 8);
            cvt_split2_h(f0.x, f0.y, ah[0], al[0]);
            cvt_split2_h(f1.x, f1.y, ah[1], al[1]);
            cvt_split2_h(f2.x, f2.y, ah[2], al[2]);
            cvt_split2_h(f3.x, f3.y, ah[3], al[3]);
            #pragma unroll
            for (int j = 0; j < 8; j++) {
                const int nr = 8 * j + gr;
                const char* pB = sW + (long)nr * PJ_WROW + (kb + c2) * 2;
                uint32_t bh0 = *(const uint32_t*)(pB);
                uint32_t bh1 = *(const uint32_t*)(pB + 16);
                MMA_F16(acc[j], ah, bh0, bh1);
                MMA_F16(acc[j], al, bh0, bh1);
            }
        }
        __syncthreads();   // all warps done with stage s before it is re-filled
    }

    {
        const int mr = w * 16 + gr;
        #pragma unroll
        for (int j = 0; j < 8; j++) {
            float* cp = Cp + (long)mr * Hh + bn + 8 * j + c2;
            *(float2*)cp            = make_float2(acc[j][0], acc[j][1]);
            *(float2*)(cp + 8 * Hh) = make_float2(acc[j][2], acc[j][3]);
        }
    }
}

// ---------------------------------------------------------------------------
// S1: balanced scoring pass (unchanged). Raw scores -> g_attn.
// ---------------------------------------------------------------------------
#define S1_QT 65
#define S1_KT 18
#define S1_SMEM (Hh * S1_QT * 4 + Hh * S1_KT * 4)

__global__ __launch_bounds__(256) void score_pass(
        const float* __restrict__ Wv, const int* __restrict__ vlens) {
    const int kt = blockIdx.x;
    const int b  = blockIdx.y;
    const int vl = vlens[b];
    if (kt * 16 >= vl) return;

    extern __shared__ float s1[];
    float* qt = s1;                        // [256][65]
    float* ktl = s1 + Hh * S1_QT;          // [256][18], [h][16] = Wv[h]

    const int tid  = threadIdx.x;
    const int lane = tid & 31;
    const int w    = tid >> 5;

    {
        const float4* src = (const float4*)(g_qh + (long)b * Qq * Hh);
        #pragma unroll
        for (int r = 0; r < 16; r++) {
            int i = tid + 256 * r;
            int q = i >> 6, h0 = (i & 63) << 2;
            float4 v = src[i];
            qt[(h0 + 0) * S1_QT + q] = v.x;
            qt[(h0 + 1) * S1_QT + q] = v.y;
            qt[(h0 + 2) * S1_QT + q] = v.z;
            qt[(h0 + 3) * S1_QT + q] = v.w;
        }
    }
    {
        const float4* src = (const float4*)(g_kh + ((long)b * KK + kt * 16) * Hh);
        #pragma unroll
        for (int r = 0; r < 4; r++) {
            int i = tid + 256 * r;
            int k = i >> 6, h0 = (i & 63) << 2;
            float4 v = src[i];
            ktl[(h0 + 0) * S1_KT + k] = v.x;
            ktl[(h0 + 1) * S1_KT + k] = v.y;
            ktl[(h0 + 2) * S1_KT + k] = v.z;
            ktl[(h0 + 3) * S1_KT + k] = v.w;
        }
    }
    ktl[tid * S1_KT + 16] = Wv[tid];
    __syncthreads();

    float a00 = 0.f, a01 = 0.f, a10 = 0.f, a11 = 0.f;
    #pragma unroll 4
    for (int h = 0; h < Hh; h++) {
        const float* kr = ktl + h * S1_KT;
        float2 kv = *(const float2*)(kr + 2 * w);
        float  wv = kr[16];
        float  qa = qt[h * S1_QT + lane];
        float  qb = qt[h * S1_QT + lane + 32];
        a00 = fmaf(wv, tanhx(qa + kv.x), a00);
        a01 = fmaf(wv, tanhx(qa + kv.y), a01);
        a10 = fmaf(wv, tanhx(qb + kv.x), a10);
        a11 = fmaf(wv, tanhx(qb + kv.y), a11);
    }

    float* d0 = g_attn + ((long)b * Qq + lane) * KK + kt * 16 + 2 * w;
    *(float2*)d0              = make_float2(a00, a01);
    *(float2*)(d0 + 32 * KK)  = make_float2(a10, a11);
}

// ---------------------------------------------------------------------------
// S2: masked softmax over g_attn rows, in place. float4 loads/stores.
// grid = Bb*16 = 256, block = 128.
// ---------------------------------------------------------------------------
__global__ __launch_bounds__(128) void softmax_k(const int* __restrict__ vlens) {
    const int b    = blockIdx.x >> 4;
    const int q0   = (blockIdx.x & 15) * 4;
    const int lane = threadIdx.x & 31;
    const int w    = threadIdx.x >> 5;
    const int vl   = vlens[b];

    float* row = g_attn + ((long)b * Qq + q0 + w) * KK;
    float4* r4 = (float4*)row;

    float vals[16];
    float mx = -3.0e38f;
    #pragma unroll
    for (int i = 0; i < 4; i++) {
        float4 v = r4[i * 32 + lane];
        int k0 = 128 * i + 4 * lane;
        float t[4] = {v.x, v.y, v.z, v.w};
        #pragma unroll
        for (int j = 0; j < 4; j++) {
            float x = (k0 + j < vl) ? t[j] : -1e6f;
            vals[i * 4 + j] = x;
            mx = fmaxf(mx, x);
        }
    }
    #pragma unroll
    for (int off = 16; off; off >>= 1)
        mx = fmaxf(mx, __shfl_xor_sync(0xffffffffu, mx, off));
    float sum = 0.f;
    #pragma unroll
    for (int i = 0; i < 16; i++) {
        float e = __expf(vals[i] - mx);   // masked -> exactly 0
        vals[i] = e;
        sum += e;
    }
    #pragma unroll
    for (int off = 16; off; off >>= 1)
        sum += __shfl_xor_sync(0xffffffffu, sum, off);
    const float inv = __fdividef(1.f, sum);
    #pragma unroll
    for (int i = 0; i < 4; i++) {
        float4 o = make_float4(vals[i * 4 + 0] * inv, vals[i * 4 + 1] * inv,
                               vals[i * 4 + 2] * inv, vals[i * 4 + 3] * inv);
        r4[i * 32 + lane] = o;
    }
}

// ---------------------------------------------------------------------------
// Tensor-core AV GEMM, fp16x2 split (attn = hi+lo, values = hi only),
// double-buffered. CTA 64(M) x 32(N), 4 warps, warp = 16x32.
// grid = (Bb, Dd/32): batch fastest -> vl-balanced residency.
// ---------------------------------------------------------------------------
#define RS 72
#define AV_AH 0
#define AV_AL (64 * RS)
#define AV_BH (2 * 64 * RS)
#define AV_STG (AV_BH + 32 * RS)            // 11520 bytes
#define AV_SMEM (2 * AV_STG)

__global__ __launch_bounds__(128) void av_mma(
        const float* __restrict__ values, float* __restrict__ out,
        const int* __restrict__ vlens) {
    extern __shared__ __align__(16) char sma[];
    const int tid = threadIdx.x, lane = tid & 31, w = tid >> 5;
    const int b = blockIdx.x, bn = blockIdx.y * 32;

    const float* Ap = g_attn + (long)b * Qq * KK;
    const float* Bp = values + (long)b * KK * Dd;
    float* Cp       = out + (long)b * Qq * Dd;
    const int nsl   = (((vlens[b] + 31) & ~31) >> 5);

    const int gr = lane >> 2;
    const int c2 = (lane & 3) << 1;

    float acc[4][4] = {};
    float4 ra[4], rw[2];

    auto ldg_slice = [&](int s) {
        const float* Ab = Ap + s * 32;
        const float* Bb2 = Bp + (long)s * 32 * Dd;
        #pragma unroll
        for (int r = 0; r < 4; r++) {
            int i = tid + 128 * r;
            ra[r] = *(const float4*)(Ab + (long)(i >> 3) * KK + ((i & 7) << 2));
        }
        #pragma unroll
        for (int r = 0; r < 2; r++) {
            int i = tid + 128 * r;
            rw[r] = *(const float4*)(Bb2 + (long)(i >> 3) * Dd + bn + ((i & 7) << 2));
        }
    };
    auto sts_slice = [&](char* sb) {
        #pragma unroll
        for (int r = 0; r < 4; r++) {
            int i = tid + 128 * r;
            int row = i >> 3, kc = (i & 7) << 2;
            uint32_t h0, l0, h1, l1;
            cvt_split2_h(ra[r].x, ra[r].y, h0, l0);
            cvt_split2_h(ra[r].z, ra[r].w, h1, l1);
            *(uint2*)(sb + AV_AH + row * RS + kc * 2) = make_uint2(h0, h1);
            *(uint2*)(sb + AV_AL + row * RS + kc * 2) = make_uint2(l0, l1);
        }
        #pragma unroll
        for (int r = 0; r < 2; r++) {
            int i = tid + 128 * r;
            int k = i >> 3, nc = (i & 7) << 2;
            float v[4] = {rw[r].x, rw[r].y, rw[r].z, rw[r].w};
            #pragma unroll
            for (int j = 0; j < 4; j++)
                *(uint16_t*)(sb + AV_BH + (nc + j) * RS + k * 2) = f2h(v[j]);
        }
    };

    ldg_slice(0);
    sts_slice(sma);
    __syncthreads();

    for (int s = 0; s < nsl; s++) {
        const char* sb = sma + (s & 1) * AV_STG;
        if (s + 1 < nsl) ldg_slice(s + 1);

        #pragma unroll
        for (int kh = 0; kh < 2; kh++) {
            const int kb = kh * 16;
            uint32_t ah[4], al[4];
            const int mr = w * 16 + gr;
            const char* pA = sb + (long)mr * RS + (kb + c2) * 2;
            ah[0] = *(const uint32_t*)(pA + AV_AH);
            ah[1] = *(const uint32_t*)(pA + AV_AH + 8 * RS);
            ah[2] = *(const uint32_t*)(pA + AV_AH + 16);
            ah[3] = *(const uint32_t*)(pA + AV_AH + 8 * RS + 16);
            al[0] = *(const uint32_t*)(pA + AV_AL);
            al[1] = *(const uint32_t*)(pA + AV_AL + 8 * RS);
            al[2] = *(const uint32_t*)(pA + AV_AL + 16);
            al[3] = *(const uint32_t*)(pA + AV_AL + 8 * RS + 16);
            #pragma unroll
            for (int j = 0; j < 4; j++) {
                const int nr = 8 * j + gr;
                const char* pB = sb + (long)nr * RS + (kb + c2) * 2;
                uint32_t bh0 = *(const uint32_t*)(pB + AV_BH);
                uint32_t bh1 = *(const uint32_t*)(pB + AV_BH + 16);
                MMA_F16(acc[j], ah, bh0, bh1);
                MMA_F16(acc[j], al, bh0, bh1);
            }
        }

        if (s + 1 < nsl) sts_slice(sma + ((s + 1) & 1) * AV_STG);
        __syncthreads();
    }

    {
        const int mr = w * 16 + gr;
        #pragma unroll
        for (int j = 0; j < 4; j++) {
            float* cp = Cp + (long)mr * Dd + bn + 8 * j + c2;
            *(float2*)cp            = make_float2(acc[j][0], acc[j][1]);
            *(float2*)(cp + 8 * Dd) = make_float2(acc[j][2], acc[j][3]);
        }
    }
}

extern "C" void kernel_launch(void* const* d_in, const int* in_sizes, int n_in,
                              void* d_out, int out_size) {
    const float* queries = (const float*)d_in[0];  // [16,64,512]
    const float* keys    = (const float*)d_in[1];  // [16,512,512]
    const float* values  = (const float*)d_in[2];  // [16,512,512]
    const int*   vlens   = (const int*)d_in[3];    // [16]
    const float* Wq      = (const float*)d_in[4];  // [512,256]
    const float* Wk      = (const float*)d_in[5];  // [512,256]
    const float* Wv      = (const float*)d_in[6];  // [256]
    float* out = (float*)d_out;                    // [16,64,512]

    cudaFuncSetAttribute(proj_mma,
                         cudaFuncAttributeMaxDynamicSharedMemorySize, PROJ_SMEM);
    cudaFuncSetAttribute(score_pass,
                         cudaFuncAttributeMaxDynamicSharedMemorySize, S1_SMEM);
    cudaFuncSetAttribute(av_mma,
                         cudaFuncAttributeMaxDynamicSharedMemorySize, AV_SMEM);

    prep_w<<<256, 256>>>(Wq, Wk);
    proj_mma<<<dim3(Hh / 64, (Bb * Qq + Bb * KK) / 128), 256, PROJ_SMEM>>>(
        queries, keys, vlens);
    score_pass<<<dim3(KK / 16, Bb), 256, S1_SMEM>>>(Wv, vlens);
    softmax_k<<<Bb * 16, 128>>>(vlens);
    av_mma<<<dim3(Bb, Dd / 32), 128, AV_SMEM>>>(values, out, vlens);
}